// round 4
// baseline (speedup 1.0000x reference)
#include <cuda_runtime.h>
#include <cuda_bf16.h>
#include <math.h>

// ---------------- problem constants ----------------
#define NB      512
#define ND      32
#define NLAT    128
#define NSMALL  500
#define NMID    2000
#define NITEMS  50000
#define NUSERS  2000
#define TWOK    40
#define KOUT    20

// expected element counts
#define SZ_X      (NB*ND)            // 16384
#define SZ_MASK   (NB*NITEMS)        // 25600000
#define SZ_WPRIOR (ND*NLAT)          // 4096
#define SZ_WSDEC  (NLAT*NSMALL)      // 64000
#define SZ_WMDEC  (NLAT*NMID)        // 256000
#define SZ_WMAP   (ND*3)             // 96
#define SZ_R      (NUSERS*NITEMS)    // 100000000
#define SZ_P      (NUSERS*ND)        // 64000
#define SZ_TMAP   (NSMALL)           // 500
#define SZ_MMAP   (NMID)             // 2000

// ---------------- device scratch (static; no allocation) ----------------
__device__ float g_sim[NB * NUSERS];          // softmax similarities  [512,2000]
__device__ float g_ps [NB * 512];             // masked small preds    [512,500] (pad 512)
__device__ float g_pm [NB * 2048];            // masked mid preds      [512,2000] (pad 2048)
__device__ float g_probs[NB * 4];             // mapper softmax        [512,3]
__device__ float g_kp [(size_t)NB * NITEMS];  // knn predictions       [512,50000]  ~102MB
__device__ float g_cval[NB * 64];             // knn top-40 values
__device__ int   g_cidx[NB * 64];             // knn top-40 indices
__device__ int   g_ccnt[NB];                  // knn candidate counts

// =====================================================================
// Kernel 1: per-row small math
// =====================================================================
__global__ __launch_bounds__(256)
void prep_kernel(const float* __restrict__ X, const float* __restrict__ mask,
                 const float* __restrict__ Wsp, const float* __restrict__ Wsd,
                 const float* __restrict__ Wmp, const float* __restrict__ Wmd,
                 const float* __restrict__ Wmap, const float* __restrict__ P,
                 const int* __restrict__ top_map, const int* __restrict__ mid_map)
{
    int row = blockIdx.x;
    int tid = threadIdx.x;

    __shared__ float sx[ND];
    __shared__ float hs[NLAT];
    __shared__ float hm[NLAT];
    __shared__ float lg[NUSERS];
    __shared__ float red[256];

    if (tid < ND) sx[tid] = X[row * ND + tid];
    __syncthreads();

    // latent vectors (threads 0..127 -> small prior, 128..255 -> mid prior)
    if (tid < NLAT) {
        float a = 0.f;
        #pragma unroll
        for (int d = 0; d < ND; d++) a += sx[d] * Wsp[d * NLAT + tid];
        hs[tid] = a;
    } else {
        int t = tid - NLAT;
        float a = 0.f;
        #pragma unroll
        for (int d = 0; d < ND; d++) a += sx[d] * Wmp[d * NLAT + t];
        hm[t] = a;
    }
    __syncthreads();

    // small decoder (masked)
    for (int i = tid; i < NSMALL; i += 256) {
        float a = 0.f;
        #pragma unroll 8
        for (int l = 0; l < NLAT; l++) a += hs[l] * Wsd[l * NSMALL + i];
        a *= mask[(size_t)row * NITEMS + top_map[i]];
        g_ps[row * 512 + i] = a;
    }
    // mid decoder (masked)
    for (int i = tid; i < NMID; i += 256) {
        float a = 0.f;
        #pragma unroll 8
        for (int l = 0; l < NLAT; l++) a += hm[l] * Wmd[l * NMID + i];
        a *= mask[(size_t)row * NITEMS + mid_map[i]];
        g_pm[row * 2048 + i] = a;
    }

    // mapper probs
    if (tid == 0) {
        float l0 = 0.f, l1 = 0.f, l2 = 0.f;
        for (int d = 0; d < ND; d++) {
            float x = sx[d];
            l0 += x * Wmap[d * 3 + 0];
            l1 += x * Wmap[d * 3 + 1];
            l2 += x * Wmap[d * 3 + 2];
        }
        float m  = fmaxf(l0, fmaxf(l1, l2));
        float e0 = expf(l0 - m), e1 = expf(l1 - m), e2 = expf(l2 - m);
        float z  = e0 + e1 + e2;
        g_probs[row * 4 + 0] = e0 / z;
        g_probs[row * 4 + 1] = e1 / z;
        g_probs[row * 4 + 2] = e2 / z;
    }

    // user logits
    const float inv_scale = 1.0f / sqrtf((float)ND);
    for (int u = tid; u < NUSERS; u += 256) {
        float a = 0.f;
        #pragma unroll
        for (int d = 0; d < ND; d++) a += sx[d] * P[u * ND + d];
        lg[u] = a * inv_scale;
    }
    __syncthreads();

    // softmax over users
    float lm = -INFINITY;
    for (int u = tid; u < NUSERS; u += 256) lm = fmaxf(lm, lg[u]);
    red[tid] = lm; __syncthreads();
    for (int s = 128; s > 0; s >>= 1) { if (tid < s) red[tid] = fmaxf(red[tid], red[tid + s]); __syncthreads(); }
    float mx = red[0];
    __syncthreads();

    float ls = 0.f;
    for (int u = tid; u < NUSERS; u += 256) { float e = expf(lg[u] - mx); lg[u] = e; ls += e; }
    red[tid] = ls; __syncthreads();
    for (int s = 128; s > 0; s >>= 1) { if (tid < s) red[tid] += red[tid + s]; __syncthreads(); }
    float z = red[0];

    float invz = 1.0f / z;
    for (int u = tid; u < NUSERS; u += 256) g_sim[row * NUSERS + u] = lg[u] * invz;
}

// =====================================================================
// Kernel 2: fp32 SGEMM  g_kp[512,50000] = g_sim[512,2000] @ R[2000,50000]
// =====================================================================
__global__ __launch_bounds__(256)
void gemm_kernel(const float* __restrict__ Bmat)
{
    const int N = NITEMS, K = NUSERS;
    __shared__ float As[16][132];   // transposed, padded
    __shared__ float Bs[16][128];

    int tid  = threadIdx.x;
    int bcol = blockIdx.x * 128;
    int brow = blockIdx.y * 128;

    int a_row = tid >> 2;          // 0..63
    int a_col = (tid & 3) << 2;    // 0,4,8,12
    int b_row = tid >> 5;          // 0..7
    int b_col = (tid & 31) << 2;   // 0..124

    int ty = (tid >> 4) << 3;      // 0..120 step 8 (M)
    int tx = (tid & 15) << 3;      // 0..120 step 8 (N)

    float acc[8][8];
    #pragma unroll
    for (int i = 0; i < 8; i++)
        #pragma unroll
        for (int j = 0; j < 8; j++) acc[i][j] = 0.f;

    for (int kt = 0; kt < K; kt += 16) {
        float4 a0 = *(const float4*)&g_sim[(size_t)(brow + a_row)      * K + kt + a_col];
        float4 a1 = *(const float4*)&g_sim[(size_t)(brow + a_row + 64) * K + kt + a_col];

        float4 b0, b1;
        int gc = bcol + b_col;
        if (gc + 3 < N) {
            b0 = *(const float4*)&Bmat[(size_t)(kt + b_row)     * N + gc];
            b1 = *(const float4*)&Bmat[(size_t)(kt + b_row + 8) * N + gc];
        } else {
            float t0[4], t1[4];
            #pragma unroll
            for (int j = 0; j < 4; j++) {
                int c = gc + j;
                t0[j] = (c < N) ? Bmat[(size_t)(kt + b_row)     * N + c] : 0.f;
                t1[j] = (c < N) ? Bmat[(size_t)(kt + b_row + 8) * N + c] : 0.f;
            }
            b0 = make_float4(t0[0], t0[1], t0[2], t0[3]);
            b1 = make_float4(t1[0], t1[1], t1[2], t1[3]);
        }

        __syncthreads();
        As[a_col + 0][a_row]      = a0.x;
        As[a_col + 1][a_row]      = a0.y;
        As[a_col + 2][a_row]      = a0.z;
        As[a_col + 3][a_row]      = a0.w;
        As[a_col + 0][a_row + 64] = a1.x;
        As[a_col + 1][a_row + 64] = a1.y;
        As[a_col + 2][a_row + 64] = a1.z;
        As[a_col + 3][a_row + 64] = a1.w;
        *(float4*)&Bs[b_row][b_col]     = b0;
        *(float4*)&Bs[b_row + 8][b_col] = b1;
        __syncthreads();

        #pragma unroll
        for (int k = 0; k < 16; k++) {
            float ar[8], br[8];
            *(float4*)(ar)     = *(const float4*)&As[k][ty];
            *(float4*)(ar + 4) = *(const float4*)&As[k][ty + 4];
            *(float4*)(br)     = *(const float4*)&Bs[k][tx];
            *(float4*)(br + 4) = *(const float4*)&Bs[k][tx + 4];
            #pragma unroll
            for (int i = 0; i < 8; i++)
                #pragma unroll
                for (int j = 0; j < 8; j++)
                    acc[i][j] += ar[i] * br[j];
        }
    }

    #pragma unroll
    for (int i = 0; i < 8; i++) {
        int r = brow + ty + i;
        #pragma unroll
        for (int j = 0; j < 8; j += 4) {
            int c = bcol + tx + j;
            if (c + 3 < N) {
                *(float4*)&g_kp[(size_t)r * N + c] =
                    make_float4(acc[i][j], acc[i][j + 1], acc[i][j + 2], acc[i][j + 3]);
            } else {
                #pragma unroll
                for (int q = 0; q < 4; q++)
                    if (c + q < N) g_kp[(size_t)r * N + c + q] = acc[i][j + q];
            }
        }
    }
}

// =====================================================================
// radix-select helper (plain shared atomics; block-collective)
// returns bit pattern of target-th largest positive value
// =====================================================================
__device__ unsigned radix_pivot(const float* __restrict__ sv, int n, int target,
                                int* hist, int* scratch, int tid, int nthr)
{
    unsigned prefix = 0u, highmask = 0u;
    for (int shift = 24; shift >= 0; shift -= 8) {
        for (int i = tid; i < 256; i += nthr) hist[i] = 0;
        __syncthreads();
        for (int i = tid; i < n; i += nthr) {
            float v = sv[i];
            unsigned u = (v > 0.f) ? __float_as_uint(v) : 0u;
            if ((u & highmask) == prefix)
                atomicAdd(&hist[(u >> shift) & 255], 1);
        }
        __syncthreads();
        if (tid == 0) {
            int cum = 0, d = 255;
            for (; d >= 0; --d) { cum += hist[d]; if (cum >= target) break; }
            if (d < 0) d = 0;
            scratch[0] = d;
            scratch[1] = target - (cum - hist[d]);
        }
        __syncthreads();
        prefix   |= ((unsigned)scratch[0]) << shift;
        highmask |= 0xFFu << shift;
        target    = scratch[1];
        __syncthreads();
    }
    return prefix;
}

// =====================================================================
// Kernel 3: per-row top-40 of knn preds (membership only)
// =====================================================================
__global__ __launch_bounds__(256)
void knn_select_kernel()
{
    int row = blockIdx.x;
    int tid = threadIdx.x;
    __shared__ int hist[256];
    __shared__ int scratch[2];
    __shared__ int s_cnt;

    const float* rowp = g_kp + (size_t)row * NITEMS;
    unsigned pivot = radix_pivot(rowp, NITEMS, TWOK, hist, scratch, tid, 256);

    if (tid == 0) s_cnt = 0;
    __syncthreads();
    for (int i = tid; i < NITEMS; i += 256) {
        float v = rowp[i];
        if (v > 0.f && __float_as_uint(v) >= pivot) {
            int p = atomicAdd(&s_cnt, 1);
            if (p < 64) {
                g_cval[row * 64 + p] = v;
                g_cidx[row * 64 + p] = i;
            }
        }
    }
    __syncthreads();
    if (tid == 0) g_ccnt[row] = min(s_cnt, 64);
}

// =====================================================================
// Kernel 4: per-row branch selection + fusion + final top-20 (ordered)
// OUTPUT IS WRITTEN AS float32 (harness output dtype) — values are the
// item indices cast to float.
// =====================================================================
__global__ __launch_bounds__(256)
void fuse_kernel(const int* __restrict__ top_map, const int* __restrict__ mid_map,
                 float* __restrict__ out)
{
    int row = blockIdx.x;
    int tid = threadIdx.x;

    __shared__ float sv[2048];
    __shared__ int   hist[256];
    __shared__ int   scratch[2];
    __shared__ int   s_npos, s_ncand, s_base;
    __shared__ int   cIdx[192];
    __shared__ float cVal[192];
    __shared__ unsigned long long keys[192];

    float p0 = g_probs[row * 4 + 0];
    float p1 = g_probs[row * 4 + 1];
    float p2 = g_probs[row * 4 + 2];

    if (tid == 0) s_ncand = 0;

    // ---------- small branch ----------
    for (int i = tid; i < NSMALL; i += 256) sv[i] = g_ps[row * 512 + i];
    if (tid == 0) s_npos = 0;
    __syncthreads();
    {
        int cp = 0;
        for (int i = tid; i < NSMALL; i += 256) cp += (sv[i] > 0.f);
        atomicAdd(&s_npos, cp);
    }
    __syncthreads();
    {
        int npos = s_npos;
        int tk = min(TWOK, npos);
        unsigned pivot = 1u;   // any positive
        if (npos > TWOK) pivot = radix_pivot(sv, NSMALL, tk, hist, scratch, tid, 256);
        __syncthreads();
        if (tk > 0) {
            for (int i = tid; i < NSMALL; i += 256) {
                float v = sv[i];
                if (v > 0.f && __float_as_uint(v) >= pivot) {
                    int p = atomicAdd(&s_ncand, 1);
                    if (p < 192) { cIdx[p] = top_map[i]; cVal[p] = v * p0; }
                }
            }
        }
    }
    __syncthreads();

    // ---------- mid branch ----------
    for (int i = tid; i < NMID; i += 256) sv[i] = g_pm[row * 2048 + i];
    if (tid == 0) s_npos = 0;
    __syncthreads();
    {
        int cp = 0;
        for (int i = tid; i < NMID; i += 256) cp += (sv[i] > 0.f);
        atomicAdd(&s_npos, cp);
    }
    __syncthreads();
    {
        int npos = s_npos;
        int tk = min(TWOK, npos);
        unsigned pivot = 1u;
        if (npos > TWOK) pivot = radix_pivot(sv, NMID, tk, hist, scratch, tid, 256);
        __syncthreads();
        if (tk > 0) {
            for (int i = tid; i < NMID; i += 256) {
                float v = sv[i];
                if (v > 0.f && __float_as_uint(v) >= pivot) {
                    int p = atomicAdd(&s_ncand, 1);
                    if (p < 192) { cIdx[p] = mid_map[i]; cVal[p] = v * p1; }
                }
            }
        }
    }
    __syncthreads();
    if (tid == 0) s_base = min(s_ncand, 192);
    __syncthreads();
    int base = s_base;

    // ---------- knn branch (accumulate on index collisions) ----------
    int kc = g_ccnt[row];
    for (int j = tid; j < kc; j += 256) {
        int   idx = g_cidx[row * 64 + j];
        float v   = g_cval[row * 64 + j] * p2;
        int found = -1;
        for (int q = 0; q < base; q++) {
            if (cIdx[q] == idx) { found = q; break; }
        }
        if (found >= 0) {
            cVal[found] += v;           // unique writer per slot (knn idx distinct)
        } else {
            int p = atomicAdd(&s_ncand, 1);
            if (p < 192) { cIdx[p] = idx; cVal[p] = v; }
        }
    }
    __syncthreads();

    // ---------- final top-20 with jax tie rule ----------
    int n = min(s_ncand, 192);
    for (int c = tid; c < n; c += 256) {
        keys[c] = (((unsigned long long)__float_as_uint(cVal[c])) << 32)
                  | (unsigned)(0xFFFFFFFFu - (unsigned)cIdx[c]);
    }
    __syncthreads();
    for (int c = tid; c < n; c += 256) {
        unsigned long long kcv = keys[c];
        int rank = 0;
        for (int o = 0; o < n; o++) rank += (keys[o] > kcv);
        if (rank < KOUT) out[row * KOUT + rank] = (float)cIdx[c];
    }
    __syncthreads();

    // safety: if fewer than KOUT candidates, fill with smallest non-candidate
    // indices (value 0 entries, jax tie rule). Practically unreachable (n>=40).
    if (tid == 0 && n < KOUT) {
        int fill = n;
        for (int idx = 0; idx < NITEMS && fill < KOUT; idx++) {
            bool used = false;
            for (int q = 0; q < n; q++) if (cIdx[q] == idx) { used = true; break; }
            if (!used) out[row * KOUT + fill++] = (float)idx;
        }
    }
}

// =====================================================================
// launch: resolve input ordering at runtime from in_sizes
// =====================================================================
extern "C" void kernel_launch(void* const* d_in, const int* in_sizes, int n_in,
                              void* d_out, int out_size)
{
    // default: dict/signature order
    int iX=0, iMask=1, iWsp=2, iWsd=3, iWmp=4, iWmd=5, iWmap=6, iR=7, iP=8, iTmap=9, iMmap=10;

    if (in_sizes[0] == SZ_X && in_sizes[1] == SZ_MASK && in_sizes[7] == SZ_R) {
        // dict order confirmed (k, if present, is last and ignored)
    } else if (in_sizes[0] == SZ_WMAP && in_sizes[1] == SZ_WMDEC) {
        // alphabetical: W_mapper, W_mdec, W_mprior, W_sdec, W_sprior, X, [k,] mask, mid_map, top_map, user_personalities, user_ratings
        iWmap = 0; iWmd = 1; iWmp = 2; iWsd = 3; iWsp = 4; iX = 5;
        int off = (n_in >= 12 && in_sizes[6] == 1) ? 1 : 0;
        iMask = 6 + off; iMmap = 7 + off; iTmap = 8 + off; iP = 9 + off; iR = 10 + off;
    } else {
        // greedy size-based assignment; duplicate sizes resolved by occurrence order
        int seen4096 = 0, seen64000 = 0;
        for (int i = 0; i < n_in; i++) {
            int s = in_sizes[i];
            if      (s == SZ_X)      iX = i;
            else if (s == SZ_MASK)   iMask = i;
            else if (s == SZ_WMDEC)  iWmd = i;
            else if (s == SZ_WMAP)   iWmap = i;
            else if (s == SZ_R)      iR = i;
            else if (s == SZ_TMAP)   iTmap = i;
            else if (s == SZ_MMAP)   iMmap = i;
            else if (s == SZ_WPRIOR) { if (seen4096++ == 0) iWsp = i; else iWmp = i; }
            else if (s == SZ_WSDEC)  { if (seen64000++ == 0) iWsd = i; else iP = i; }
        }
    }

    const float* X    = (const float*)d_in[iX];
    const float* mask = (const float*)d_in[iMask];
    const float* Wsp  = (const float*)d_in[iWsp];
    const float* Wsd  = (const float*)d_in[iWsd];
    const float* Wmp  = (const float*)d_in[iWmp];
    const float* Wmd  = (const float*)d_in[iWmd];
    const float* Wmap = (const float*)d_in[iWmap];
    const float* R    = (const float*)d_in[iR];
    const float* P    = (const float*)d_in[iP];
    const int*   tmap = (const int*)d_in[iTmap];
    const int*   mmap = (const int*)d_in[iMmap];
    float* out = (float*)d_out;

    prep_kernel<<<NB, 256>>>(X, mask, Wsp, Wsd, Wmp, Wmd, Wmap, P, tmap, mmap);

    dim3 ggrid((NITEMS + 127) / 128, NB / 128);
    gemm_kernel<<<ggrid, 256>>>(R);

    knn_select_kernel<<<NB, 256>>>();

    fuse_kernel<<<NB, 256>>>(tmap, mmap, out);
}